// round 5
// baseline (speedup 1.0000x reference)
#include <cuda_runtime.h>

#define B 16
#define S 4096
#define H 1024
#define JCHUNK 128

// ---- device scratch (no allocations allowed) ----
__device__ float g_scores[B * S];
__device__ float g_m[B];
__device__ float g_l[B];
__device__ int   g_start[B];
__device__ int   g_qlen[B];
__device__ int   g_maxlen;

// K0: decode query_indices, compute per-batch start/qlen and global max_len.
// Handles BOTH int32 and int64 storage: if the buffer is int64 (little-endian,
// values < 2^31), every odd 32-bit word is the zero high-half.
__global__ void k0_setup(const int* __restrict__ qi32) {
    if (threadIdx.x == 0) {
        bool is64 = true;
        for (int i = 1; i < 32; i += 2) {
            if (qi32[i] != 0) { is64 = false; break; }
        }
        int maxlen = 0;
        for (int b = 0; b < B; b++) {
            int s, e;
            if (is64) { s = qi32[4 * b];  e = qi32[4 * b + 2]; }
            else      { s = qi32[2 * b];  e = qi32[2 * b + 1]; }
            g_start[b] = s;
            g_qlen[b]  = e - s;
            int ml = e + 1 - s;
            if (ml > maxlen) maxlen = ml;
        }
        g_maxlen = maxlen;
    }
}

// K1: scores[b, j] = am[b] * dot(hs[b, start+j, :], w)  for j < qlen
//     scores[b, j] = 0                                   for qlen <= j < max_len
// One warp per row, 8 rows per 256-thread block. w staged in smem.
__global__ void k1_scores(const float* __restrict__ hs,
                          const float* __restrict__ am,
                          const float* __restrict__ w) {
    __shared__ float sw[H];
    const int b = blockIdx.y;
    const int jbase = blockIdx.x * 8;
    const int maxlen = g_maxlen;
    if (jbase >= maxlen) return;

    for (int i = threadIdx.x; i < H; i += blockDim.x) sw[i] = w[i];
    __syncthreads();

    const int warp = threadIdx.x >> 5;
    const int lane = threadIdx.x & 31;
    const int j = jbase + warp;
    if (j >= maxlen) return;

    const int qlen = g_qlen[b];
    float sc = 0.0f;
    if (j < qlen) {
        const float* x = hs + ((size_t)(b * S + g_start[b] + j)) * H;
        float acc = 0.0f;
#pragma unroll
        for (int it = 0; it < 8; it++) {
            const int idx = (lane + it * 32) * 4;
            float4 xv = *reinterpret_cast<const float4*>(x + idx);
            float4 wv = *reinterpret_cast<const float4*>(sw + idx);
            acc += xv.x * wv.x + xv.y * wv.y + xv.z * wv.z + xv.w * wv.w;
        }
#pragma unroll
        for (int o = 16; o; o >>= 1) acc += __shfl_xor_sync(0xffffffffu, acc, o);
        sc = am[b] * acc;
    }
    if (lane == 0) g_scores[b * S + j] = sc;
}

// K2: per-batch softmax statistics (max, sum of exp) over [0, max_len); zero d_out.
__global__ void k2_softmax(float* __restrict__ out) {
    const int b = blockIdx.x;
    const int maxlen = g_maxlen;
    const int tid = threadIdx.x;
    __shared__ float red[256];

    float m = -1e30f;
    for (int j = tid; j < maxlen; j += 256) m = fmaxf(m, g_scores[b * S + j]);
    red[tid] = m;
    __syncthreads();
    for (int o = 128; o; o >>= 1) {
        if (tid < o) red[tid] = fmaxf(red[tid], red[tid + o]);
        __syncthreads();
    }
    m = red[0];
    __syncthreads();

    float l = 0.0f;
    for (int j = tid; j < maxlen; j += 256) l += expf(g_scores[b * S + j] - m);
    red[tid] = l;
    __syncthreads();
    for (int o = 128; o; o >>= 1) {
        if (tid < o) red[tid] += red[tid + o];
        __syncthreads();
    }

    if (tid == 0) {
        g_m[b] = m;
        g_l[b] = red[0];
    }
    // zero-init output rows for this batch (d_out is poisoned by the harness)
    for (int h = tid; h < H; h += 256) out[b * H + h] = 0.0f;
}

// K3: out[b, h] += sum_{j in chunk} p[j] * am[b] * hs[b, start+j, h]
// grid = (S/JCHUNK, H/256, B); probabilities staged in smem; coalesced columns.
__global__ void k3_agg(const float* __restrict__ hs,
                       const float* __restrict__ am,
                       float* __restrict__ out) {
    const int b = blockIdx.z;
    const int qlen = g_qlen[b];
    const int jbase = blockIdx.x * JCHUNK;
    if (jbase >= qlen) return;

    const int nj = min(JCHUNK, qlen - jbase);
    __shared__ float p[JCHUNK];

    const float m = g_m[b];
    const float inv_l = 1.0f / g_l[b];
    const float amb = am[b];
    for (int jj = threadIdx.x; jj < nj; jj += 256)
        p[jj] = expf(g_scores[b * S + jbase + jj] - m) * inv_l * amb;
    __syncthreads();

    const int h = blockIdx.y * 256 + threadIdx.x;
    const float* x = hs + ((size_t)(b * S + g_start[b] + jbase)) * H + h;

    float acc = 0.0f;
#pragma unroll 8
    for (int jj = 0; jj < nj; jj++) acc += p[jj] * x[(size_t)jj * H];

    atomicAdd(&out[b * H + h], acc);
}

extern "C" void kernel_launch(void* const* d_in, const int* in_sizes, int n_in,
                              void* d_out, int out_size) {
    // Identify inputs by element count (robust to metadata ordering):
    //   hidden_states: B*S*H = 67108864 (f32)
    //   query_indices: 2*B   = 32       (i32 or i64 — detected in k0)
    //   attention_mask: B    = 16       (f32)
    //   w:             H     = 1024     (f32)
    const float* hs = nullptr;
    const int*   qi = nullptr;
    const float* am = nullptr;
    const float* w  = nullptr;
    for (int i = 0; i < n_in; i++) {
        switch (in_sizes[i]) {
            case B * S * H: hs = (const float*)d_in[i]; break;
            case 2 * B:     qi = (const int*)d_in[i];   break;
            case B:         am = (const float*)d_in[i]; break;
            case H:         w  = (const float*)d_in[i]; break;
        }
    }
    float* out = (float*)d_out;

    k0_setup<<<1, 32>>>(qi);

    dim3 g1(S / 8, B);
    k1_scores<<<g1, 256>>>(hs, am, w);

    k2_softmax<<<B, 256>>>(out);

    dim3 g3((S + JCHUNK - 1) / JCHUNK, H / 256, B);
    k3_agg<<<g3, 256>>>(hs, am, out);
}

// round 6
// speedup vs baseline: 1.0793x; 1.0793x over previous
#include <cuda_runtime.h>
#include <math.h>

#define B 16
#define S 4096
#define H 1024
#define JC 64                 // rows per block chunk
#define NCHUNK (S / JC)       // 64 chunks per batch
#define NWARP 8

// ---- device scratch (no allocations allowed) ----
__device__ int   g_start[B];
__device__ int   g_qlen[B];
__device__ int   g_maxlen;
__device__ float g_pm[B * NCHUNK];              // per-chunk running max (-inf if empty)
__device__ float g_pl[B * NCHUNK];              // per-chunk denom partial
__device__ float g_pacc[(size_t)B * NCHUNK * H]; // per-chunk numerator partial (4 MB)

// K0: decode query_indices (int32 or int64 storage, auto-detected).
__global__ void k0_setup(const int* __restrict__ qi32) {
    if (threadIdx.x == 0) {
        bool is64 = true;
        for (int i = 1; i < 32; i += 2)
            if (qi32[i] != 0) { is64 = false; break; }
        int maxlen = 0;
        for (int b = 0; b < B; b++) {
            int s, e;
            if (is64) { s = qi32[4 * b]; e = qi32[4 * b + 2]; }
            else      { s = qi32[2 * b]; e = qi32[2 * b + 1]; }
            g_start[b] = s;
            g_qlen[b]  = e - s;
            int ml = e + 1 - s;
            if (ml > maxlen) maxlen = ml;
        }
        g_maxlen = maxlen;
    }
}

// K1: fused single-pass. Block = (batch b, chunk of JC rows), 8 warps.
// Each warp: loads a full row into registers, scores it (dot w, shfl-reduce),
// online-softmax update of warp-private acc[H] held in registers.
// No block barriers in the mainloop. Rows read from DRAM exactly once.
__global__ void __launch_bounds__(256) k_main(const float* __restrict__ hs,
                                              const float* __restrict__ am,
                                              const float* __restrict__ w) {
    __shared__ float sw[H];
    __shared__ float sm_m[NWARP];
    __shared__ float sm_l[NWARP];
    __shared__ float sm_acc[NWARP][H];

    const int b = blockIdx.y;
    const int chunk = blockIdx.x;
    const int pidx = b * NCHUNK + chunk;
    const int tid = threadIdx.x;
    const int qlen = g_qlen[b];
    const int jbase = chunk * JC;

    if (jbase >= qlen) {
        if (tid == 0) { g_pm[pidx] = -INFINITY; g_pl[pidx] = 0.0f; }
        return;
    }

    for (int i = tid; i < H; i += 256) sw[i] = w[i];
    __syncthreads();

    const int warp = tid >> 5;
    const int lane = tid & 31;
    const int jend = min(jbase + JC, qlen);
    const int start = g_start[b];
    const float amb = am[b];
    const float4* sw4 = (const float4*)sw;

    float m = -INFINITY;
    float l = 0.0f;
    float4 acc[8];
#pragma unroll
    for (int i = 0; i < 8; i++) acc[i] = make_float4(0.f, 0.f, 0.f, 0.f);

    for (int j = jbase + warp; j < jend; j += NWARP) {
        const float4* x = (const float4*)(hs + ((size_t)(b * S + start + j)) * H);
        float4 r[8];
#pragma unroll
        for (int i = 0; i < 8; i++) r[i] = x[lane + i * 32];   // 8 LDG.128 in flight

        float d0 = 0.f, d1 = 0.f;
#pragma unroll
        for (int i = 0; i < 8; i += 2) {
            float4 w0 = sw4[lane + i * 32];
            float4 w1 = sw4[lane + (i + 1) * 32];
            d0 += r[i].x * w0.x + r[i].y * w0.y + r[i].z * w0.z + r[i].w * w0.w;
            d1 += r[i + 1].x * w1.x + r[i + 1].y * w1.y + r[i + 1].z * w1.z + r[i + 1].w * w1.w;
        }
        float dot = d0 + d1;
#pragma unroll
        for (int o = 16; o; o >>= 1) dot += __shfl_xor_sync(0xffffffffu, dot, o);

        const float s = amb * dot;
        const float mn = fmaxf(m, s);
        const float fac = __expf(m - mn);   // first iter: exp(-inf) = 0
        const float p = __expf(s - mn);
        l = l * fac + p;
#pragma unroll
        for (int i = 0; i < 8; i++) {
            acc[i].x = acc[i].x * fac + p * r[i].x;
            acc[i].y = acc[i].y * fac + p * r[i].y;
            acc[i].z = acc[i].z * fac + p * r[i].z;
            acc[i].w = acc[i].w * fac + p * r[i].w;
        }
        m = mn;
    }

    // ---- merge 8 warp partials -> 1 block partial ----
    if (lane == 0) { sm_m[warp] = m; sm_l[warp] = l; }
    __syncthreads();

    float M = sm_m[0];
#pragma unroll
    for (int wi = 1; wi < NWARP; wi++) M = fmaxf(M, sm_m[wi]);
    float L = 0.0f;
#pragma unroll
    for (int wi = 0; wi < NWARP; wi++) {
        float lw = sm_l[wi];
        if (lw > 0.0f) L += lw * __expf(sm_m[wi] - M);
    }

    const float facw = (l > 0.0f) ? __expf(m - M) : 0.0f;  // empty warp: m=-inf
    float4* myrow = (float4*)&sm_acc[warp][0];
#pragma unroll
    for (int i = 0; i < 8; i++) {
        float4 v = acc[i];
        v.x *= facw; v.y *= facw; v.z *= facw; v.w *= facw;
        myrow[lane + i * 32] = v;
    }
    __syncthreads();

    // thread tid owns h = tid*4 .. tid*4+3
    float4 sum = make_float4(0.f, 0.f, 0.f, 0.f);
#pragma unroll
    for (int wi = 0; wi < NWARP; wi++) {
        float4 v = ((const float4*)&sm_acc[wi][0])[tid];
        sum.x += v.x; sum.y += v.y; sum.z += v.z; sum.w += v.w;
    }
    ((float4*)(g_pacc + (size_t)pidx * H))[tid] = sum;

    if (tid == 0) { g_pm[pidx] = M; g_pl[pidx] = L; }
}

// K2: combine NCHUNK partials per batch + analytic zero-score tail terms.
// M is seeded with 0 because max_len >= qlen_b + 1 for every batch (tail rows
// always exist and carry score 0).
__global__ void __launch_bounds__(256) k_comb(const float* __restrict__ am,
                                              float* __restrict__ out) {
    const int b = blockIdx.x;
    const int tid = threadIdx.x;
    const int qlen = g_qlen[b];
    const int maxlen = g_maxlen;
    const float count = (float)(maxlen - qlen);

    const float* pm = g_pm + b * NCHUNK;
    const float* pl = g_pl + b * NCHUNK;

    float M = 0.0f;
#pragma unroll 8
    for (int c = 0; c < NCHUNK; c++) M = fmaxf(M, pm[c]);

    float L = count * __expf(-M);
#pragma unroll 8
    for (int c = 0; c < NCHUNK; c++) {
        float lc = pl[c];
        if (lc > 0.0f) L += lc * __expf(pm[c] - M);
    }

    float4 sum = make_float4(0.f, 0.f, 0.f, 0.f);
    for (int c = 0; c < NCHUNK; c++) {
        float lc = pl[c];
        if (lc > 0.0f) {
            float f = __expf(pm[c] - M);
            float4 v = ((const float4*)(g_pacc + ((size_t)(b * NCHUNK + c)) * H))[tid];
            sum.x += f * v.x; sum.y += f * v.y; sum.z += f * v.z; sum.w += f * v.w;
        }
    }

    const float scale = am[b] / L;
    sum.x *= scale; sum.y *= scale; sum.z *= scale; sum.w *= scale;
    ((float4*)out)[b * (H / 4) + tid] = sum;
}

extern "C" void kernel_launch(void* const* d_in, const int* in_sizes, int n_in,
                              void* d_out, int out_size) {
    // Identify inputs by element count (robust to metadata ordering).
    const float* hs = nullptr;
    const int*   qi = nullptr;
    const float* am = nullptr;
    const float* w  = nullptr;
    for (int i = 0; i < n_in; i++) {
        switch (in_sizes[i]) {
            case B * S * H: hs = (const float*)d_in[i]; break;
            case 2 * B:     qi = (const int*)d_in[i];   break;
            case B:         am = (const float*)d_in[i]; break;
            case H:         w  = (const float*)d_in[i]; break;
        }
    }
    float* out = (float*)d_out;

    k0_setup<<<1, 32>>>(qi);

    dim3 g1(NCHUNK, B);
    k_main<<<g1, 256>>>(hs, am, w);

    k_comb<<<B, 256>>>(am, out);
}

// round 8
// speedup vs baseline: 1.2257x; 1.1357x over previous
#include <cuda_runtime.h>
#include <math.h>

#define B 16
#define S 4096
#define H 1024
#define JC 32                  // rows per block chunk
#define NCHUNK (S / JC)        // 128 chunks per batch
#define NWARP 4
#define NTHREAD 128

// ---- device scratch (no allocations allowed) ----
__device__ float    g_pm[B * NCHUNK];               // per-chunk max
__device__ float    g_pl[B * NCHUNK];               // per-chunk denom partial
__device__ float    g_pacc[(size_t)B * NCHUNK * H]; // per-chunk numerator (8 MB)
__device__ unsigned g_cnt[B];                       // accumulating arrival counters

// Decode query_indices: auto-detect int32 vs int64 storage (little-endian,
// values < 2^31 -> every odd 32-bit word of an int64 buffer is 0).
__device__ __forceinline__ bool qi_is64(const int* __restrict__ qi) {
    bool is64 = true;
#pragma unroll
    for (int i = 1; i < 32; i += 2)
        if (qi[i] != 0) { is64 = false; break; }
    return is64;
}
__device__ __forceinline__ void qi_decode(const int* __restrict__ qi, bool is64,
                                          int b, int& s, int& e) {
    if (is64) { s = qi[4 * b]; e = qi[4 * b + 2]; }
    else      { s = qi[2 * b]; e = qi[2 * b + 1]; }
}

// Single fused kernel: flash-style online softmax over a contiguous row window,
// rows read from DRAM exactly once; last block per batch combines partials.
__global__ void __launch_bounds__(NTHREAD) k_main(const float* __restrict__ hs,
                                                  const int*   __restrict__ qi,
                                                  const float* __restrict__ am,
                                                  const float* __restrict__ w,
                                                  float*       __restrict__ out) {
    __shared__ float sw[H];                 // w (main phase) / scratch
    __shared__ float sm_m[NWARP], sm_l[NWARP];
    __shared__ float sm_acc[NWARP][H];
    __shared__ float sred[NTHREAD];
    __shared__ float sfac[NCHUNK];
    __shared__ unsigned s_last;

    const int b     = blockIdx.y;
    const int chunk = blockIdx.x;
    const int pidx  = b * NCHUNK + chunk;
    const int tid   = threadIdx.x;
    const int warp  = tid >> 5;
    const int lane  = tid & 31;

    const bool is64 = qi_is64(qi);
    int s0, e0; qi_decode(qi, is64, b, s0, e0);
    const int qlen  = e0 - s0;
    const int jbase = chunk * JC;
    const bool active = jbase < qlen;

    if (active) {
        for (int i = tid; i < H; i += NTHREAD) sw[i] = w[i];
        __syncthreads();

        const int jend = min(jbase + JC, qlen);
        const float amb = am[b];
        const float4* sw4 = (const float4*)sw;
        const size_t rowbase = ((size_t)(b * S + s0)) * H;

        float m = -INFINITY, l = 0.0f;
        float4 acc[8];
#pragma unroll
        for (int i = 0; i < 8; i++) acc[i] = make_float4(0.f, 0.f, 0.f, 0.f);

        int j = jbase + warp;
        float4 r[8];
        if (j < jend) {
            const float4* x = (const float4*)(hs + rowbase + (size_t)j * H);
#pragma unroll
            for (int i = 0; i < 8; i++) r[i] = x[lane + i * 32];
        }
        for (; j < jend; j += NWARP) {
            // prefetch next row while current row is processed
            float4 rn[8];
            const int jn = j + NWARP;
            if (jn < jend) {
                const float4* xn = (const float4*)(hs + rowbase + (size_t)jn * H);
#pragma unroll
                for (int i = 0; i < 8; i++) rn[i] = xn[lane + i * 32];
            }

            float d0 = 0.f, d1 = 0.f;
#pragma unroll
            for (int i = 0; i < 8; i += 2) {
                float4 w0 = sw4[lane + i * 32];
                float4 w1 = sw4[lane + (i + 1) * 32];
                d0 += r[i].x * w0.x + r[i].y * w0.y + r[i].z * w0.z + r[i].w * w0.w;
                d1 += r[i+1].x * w1.x + r[i+1].y * w1.y + r[i+1].z * w1.z + r[i+1].w * w1.w;
            }
            float dot = d0 + d1;
#pragma unroll
            for (int o = 16; o; o >>= 1) dot += __shfl_xor_sync(0xffffffffu, dot, o);

            const float sc  = amb * dot;
            const float mn  = fmaxf(m, sc);
            const float fac = __expf(m - mn);        // first iter: exp(-inf)=0
            const float p   = __expf(sc - mn);
            l = l * fac + p;
#pragma unroll
            for (int i = 0; i < 8; i++) {
                acc[i].x = acc[i].x * fac + p * r[i].x;
                acc[i].y = acc[i].y * fac + p * r[i].y;
                acc[i].z = acc[i].z * fac + p * r[i].z;
                acc[i].w = acc[i].w * fac + p * r[i].w;
            }
            m = mn;
#pragma unroll
            for (int i = 0; i < 8; i++) r[i] = rn[i];
        }

        // ---- merge NWARP warp partials -> block partial ----
        if (lane == 0) { sm_m[warp] = m; sm_l[warp] = l; }
        __syncthreads();

        float M = sm_m[0];
#pragma unroll
        for (int wi = 1; wi < NWARP; wi++) M = fmaxf(M, sm_m[wi]);
        float L = 0.0f;
#pragma unroll
        for (int wi = 0; wi < NWARP; wi++) {
            float lw = sm_l[wi];
            if (lw > 0.0f) L += lw * __expf(sm_m[wi] - M);
        }
        const float facw = (l > 0.0f) ? __expf(m - M) : 0.0f;
        float4* myrow = (float4*)&sm_acc[warp][0];
#pragma unroll
        for (int i = 0; i < 8; i++) {
            float4 v = acc[i];
            v.x *= facw; v.y *= facw; v.z *= facw; v.w *= facw;
            myrow[lane + i * 32] = v;
        }
        __syncthreads();

#pragma unroll
        for (int t = tid; t < H / 4; t += NTHREAD) {
            float4 sum = make_float4(0.f, 0.f, 0.f, 0.f);
#pragma unroll
            for (int wi = 0; wi < NWARP; wi++) {
                float4 v = ((const float4*)&sm_acc[wi][0])[t];
                sum.x += v.x; sum.y += v.y; sum.z += v.z; sum.w += v.w;
            }
            ((float4*)(g_pacc + (size_t)pidx * H))[t] = sum;
        }
        if (tid == 0) { g_pm[pidx] = M; g_pl[pidx] = L; }
    }

    // ---- arrival counting; last block of batch b does the combine ----
    __syncthreads();
    __threadfence();
    if (tid == 0)
        s_last = ((atomicAdd(&g_cnt[b], 1u) & (NCHUNK - 1)) == (NCHUNK - 1)) ? 1u : 0u;
    __syncthreads();
    if (!s_last) return;
    __threadfence();

    // ===== combine for batch b =====
    int maxlen = 0;
#pragma unroll
    for (int bb = 0; bb < B; bb++) {
        int ss, ee; qi_decode(qi, is64, bb, ss, ee);
        maxlen = max(maxlen, ee + 1 - ss);
    }
    const int   nact  = min(NCHUNK, (qlen + JC - 1) / JC);   // active chunks = prefix
    const float count = (float)(maxlen - qlen);              // zero-score tail rows

    // global max (seed 0: tail rows always exist, score 0)
    sred[tid] = (tid < nact) ? g_pm[b * NCHUNK + tid] : -INFINITY;
    __syncthreads();
#pragma unroll
    for (int o = NTHREAD / 2; o; o >>= 1) {
        if (tid < o) sred[tid] = fmaxf(sred[tid], sred[tid + o]);
        __syncthreads();
    }
    const float M = fmaxf(sred[0], 0.0f);
    __syncthreads();

    // per-chunk rescale factors + denominator
    float fv = 0.0f, flp = 0.0f;
    if (tid < nact) {
        fv  = __expf(g_pm[b * NCHUNK + tid] - M);
        flp = g_pl[b * NCHUNK + tid] * fv;
    }
    sfac[tid] = fv;
    sred[tid] = flp;
    __syncthreads();
#pragma unroll
    for (int o = NTHREAD / 2; o; o >>= 1) {
        if (tid < o) sred[tid] += sred[tid + o];
        __syncthreads();
    }
    const float L = count * __expf(-M) + sred[0];

    // numerator: each thread owns float4 indices tid and tid+128 (H/4 = 256)
    float4 a0 = make_float4(0.f, 0.f, 0.f, 0.f);
    float4 a1 = make_float4(0.f, 0.f, 0.f, 0.f);
#pragma unroll 4
    for (int c = 0; c < nact; c++) {
        const float f = sfac[c];
        const float4* pa = (const float4*)(g_pacc + ((size_t)(b * NCHUNK + c)) * H);
        float4 v0 = pa[tid];
        float4 v1 = pa[tid + NTHREAD];
        a0.x += f * v0.x; a0.y += f * v0.y; a0.z += f * v0.z; a0.w += f * v0.w;
        a1.x += f * v1.x; a1.y += f * v1.y; a1.z += f * v1.z; a1.w += f * v1.w;
    }

    const float scale = am[b] / L;
    a0.x *= scale; a0.y *= scale; a0.z *= scale; a0.w *= scale;
    a1.x *= scale; a1.y *= scale; a1.z *= scale; a1.w *= scale;
    float4* o4 = (float4*)(out + (size_t)b * H);
    o4[tid]           = a0;
    o4[tid + NTHREAD] = a1;
}

extern "C" void kernel_launch(void* const* d_in, const int* in_sizes, int n_in,
                              void* d_out, int out_size) {
    // Identify inputs by element count (robust to metadata ordering).
    const float* hs = nullptr;
    const int*   qi = nullptr;
    const float* am = nullptr;
    const float* w  = nullptr;
    for (int i = 0; i < n_in; i++) {
        switch (in_sizes[i]) {
            case B * S * H: hs = (const float*)d_in[i]; break;
            case 2 * B:     qi = (const int*)d_in[i];   break;
            case B:         am = (const float*)d_in[i]; break;
            case H:         w  = (const float*)d_in[i]; break;
        }
    }
    float* out = (float*)d_out;

    dim3 grid(NCHUNK, B);
    k_main<<<grid, NTHREAD>>>(hs, qi, am, w, out);
}